// round 1
// baseline (speedup 1.0000x reference)
#include <cuda_runtime.h>

#define NB    16
#define PP    1024
#define KNB   16
#define DIMS  3
#define C_IN  128
#define C_MID 64
#define C_OUT 256
#define DMUL  2
#define C_CAT 192
#define NPTS  (NB*PP)        // 16384
#define KKDIM 256            // K*K
#define EPSV  1e-5f

// ---------------- scratch (static device allocations, allowed) ----------------
__device__ float g_lift[NPTS*KNB*C_MID];     // 64 MB: relu'd lifted features [pt][k][c]
__device__ float g_X0[NPTS*KKDIM];           // 16 MB
__device__ float g_X1[NPTS*KKDIM];
__device__ float g_X2[NPTS*KKDIM];
__device__ float g_dw[NPTS*C_CAT*DMUL];      // 24 MB
__device__ double g_sum[C_OUT];
__device__ double g_sumsq[C_OUT];
__device__ float g_scale[C_OUT];
__device__ float g_shift[C_OUT];

// ---------------- K0: zero accumulators ----------------
__global__ void k_zero() {
    int t = threadIdx.x;
    if (t < C_OUT) { g_sum[t] = 0.0; g_sumsq[t] = 0.0; }
}

// ---------------- K1: pts_local -> MLP (lifted) + relu'd conv X0 ----------------
#define PB1 8
__global__ void k_prep(const float* __restrict__ rep_pt, const float* __restrict__ pts,
                       const float* __restrict__ d1_w, const float* __restrict__ d1_b,
                       const float* __restrict__ d2_w, const float* __restrict__ d2_b,
                       const float* __restrict__ cv_w, const float* __restrict__ cv_b) {
    __shared__ float s_pl[PB1*KNB*DIMS];       // pts_local [p][k][d]
    __shared__ float s_h[PB1*KNB][C_MID];      // 32 KB
    const int t = threadIdx.x;
    const int pbase = blockIdx.x * PB1;

    for (int idx = t; idx < PB1*KNB*DIMS; idx += 256) {
        int p = idx / (KNB*DIMS);
        int rem = idx % (KNB*DIMS);
        int k = rem / DIMS, d = rem % DIMS;
        int gp = pbase + p;
        s_pl[idx] = pts[(gp*KNB + k)*DIMS + d] - rep_pt[gp*DIMS + d];
    }
    __syncthreads();

    // h = relu(pts_local @ d1_w + d1_b)
    {
        int c = t & 63;
        int rg = t >> 6;                       // 0..3, 32 rows each
        float w0 = d1_w[0*C_MID + c], w1 = d1_w[1*C_MID + c], w2 = d1_w[2*C_MID + c];
        float b = d1_b[c];
        for (int r = 0; r < 32; ++r) {
            int row = rg*32 + r;               // row = p*16 + k
            const float* pl = &s_pl[row*DIMS];
            float v = b + pl[0]*w0 + pl[1]*w1 + pl[2]*w2;
            s_h[row][c] = fmaxf(v, 0.f);
        }
    }
    __syncthreads();

    // lifted = relu(h @ d2_w + d2_b)
    {
        int c = t & 63;
        int rg = t >> 6;
        float acc[32];
        float b = d2_b[c];
        #pragma unroll
        for (int r = 0; r < 32; ++r) acc[r] = b;
        for (int kk = 0; kk < C_MID; ++kk) {
            float w = d2_w[kk*C_MID + c];
            #pragma unroll
            for (int r = 0; r < 32; ++r)
                acc[r] += s_h[rg*32 + r][kk] * w;
        }
        for (int r = 0; r < 32; ++r) {
            int row = rg*32 + r;
            g_lift[(pbase*KNB + row)*C_MID + c] = fmaxf(acc[r], 0.f);
        }
    }

    // X0 = relu(einsum('pkd,odk->po') + cv_b)   (reads only s_pl; no sync hazard)
    {
        int o = t;                              // 0..255
        float acc[PB1];
        float b = cv_b[o];
        #pragma unroll
        for (int p = 0; p < PB1; ++p) acc[p] = b;
        #pragma unroll
        for (int d = 0; d < DIMS; ++d)
            for (int k = 0; k < KNB; ++k) {
                float w = cv_w[o*(DIMS*KNB) + d*KNB + k];
                #pragma unroll
                for (int p = 0; p < PB1; ++p)
                    acc[p] += s_pl[(p*KNB + k)*DIMS + d] * w;
            }
        for (int p = 0; p < PB1; ++p)
            g_X0[(pbase + p)*KKDIM + o] = fmaxf(acc[p], 0.f);
    }
}

// ---------------- tiled SGEMM: C = act(A @ B (+bias)) ----------------
// A: [M,K] row-major.  B_IS_NK=false: B is [K,N];  true: B is [N,K].
template<bool B_IS_NK, bool RELU, bool USE_BIAS>
__global__ void k_gemm(const float* __restrict__ A, const float* __restrict__ B,
                       const float* __restrict__ bias, float* __restrict__ C,
                       int M, int Nn, int Kd) {
    const int BM = 64, BN = 64, BK = 16;
    __shared__ float As[BK][BM];
    __shared__ float Bs[BK][BN];
    const int t = threadIdx.x;                  // 256 threads
    const int tx = t & 15, ty = t >> 4;
    const int rowBase = blockIdx.y * BM;
    const int colBase = blockIdx.x * BN;
    float acc[4][4] = {};

    for (int k0 = 0; k0 < Kd; k0 += BK) {
        {   // A tile 64x16, transpose into As[k][m]
            int row = t >> 2;
            int c4 = (t & 3) * 4;
            float4 v = *reinterpret_cast<const float4*>(&A[(rowBase+row)*Kd + k0 + c4]);
            As[c4+0][row] = v.x; As[c4+1][row] = v.y; As[c4+2][row] = v.z; As[c4+3][row] = v.w;
        }
        if (!B_IS_NK) {   // B[K,N]: direct 16x64
            int r = t >> 4;
            int c4 = (t & 15) * 4;
            float4 v = *reinterpret_cast<const float4*>(&B[(k0+r)*Nn + colBase + c4]);
            *reinterpret_cast<float4*>(&Bs[r][c4]) = v;
        } else {          // B[N,K]: transpose into Bs[k][n]
            int n = t >> 2;
            int k4 = (t & 3) * 4;
            float4 v = *reinterpret_cast<const float4*>(&B[(colBase+n)*Kd + k0 + k4]);
            Bs[k4+0][n] = v.x; Bs[k4+1][n] = v.y; Bs[k4+2][n] = v.z; Bs[k4+3][n] = v.w;
        }
        __syncthreads();
        #pragma unroll
        for (int kk = 0; kk < BK; ++kk) {
            float a[4], b[4];
            #pragma unroll
            for (int i = 0; i < 4; ++i) a[i] = As[kk][ty*4+i];
            #pragma unroll
            for (int j = 0; j < 4; ++j) b[j] = Bs[kk][tx*4+j];
            #pragma unroll
            for (int i = 0; i < 4; ++i)
                #pragma unroll
                for (int j = 0; j < 4; ++j)
                    acc[i][j] += a[i]*b[j];
        }
        __syncthreads();
    }
    #pragma unroll
    for (int i = 0; i < 4; ++i) {
        int row = rowBase + ty*4 + i;
        #pragma unroll
        for (int j = 0; j < 4; ++j) {
            int col = colBase + tx*4 + j;
            float v = acc[i][j];
            if (USE_BIAS) v += bias[col];
            if (RELU) v = fmaxf(v, 0.f);
            C[row*Nn + col] = v;
        }
    }
}

// ---------------- K4: fts_X = X @ [lifted|fts], then depthwise conv -> g_dw ----------------
#define PB4 4
__global__ void k_xform(const float* __restrict__ fts,
                        const float* __restrict__ dw_w, const float* __restrict__ dw_b) {
    __shared__ float s_X[KKDIM];
    const int t = threadIdx.x;                  // 0..191 = channel c
    const int pbase = blockIdx.x * PB4;
    for (int p = 0; p < PB4; ++p) {
        int gp = pbase + p;
        for (int idx = t; idx < KKDIM; idx += 192) s_X[idx] = g_X2[gp*KKDIM + idx];
        __syncthreads();
        float fX[KNB] = {};                     // fts_X[k][c] for this c
        int c = t;
        #pragma unroll 4
        for (int j = 0; j < KNB; ++j) {
            float catv = (c < C_MID) ? g_lift[(gp*KNB + j)*C_MID + c]
                                     : fts[(gp*KNB + j)*C_IN + (c - C_MID)];
            #pragma unroll
            for (int k = 0; k < KNB; ++k)
                fX[k] += s_X[k*KNB + j] * catv;
        }
        #pragma unroll
        for (int m = 0; m < DMUL; ++m) {
            int jj = c*DMUL + m;
            float acc = dw_b[jj];
            #pragma unroll
            for (int k = 0; k < KNB; ++k)
                acc += fX[k] * dw_w[jj*KNB + k];
            g_dw[gp*(C_CAT*DMUL) + jj] = acc;
        }
        __syncthreads();
    }
}

// ---------------- K5: per-channel sum / sumsq ----------------
__global__ void k_stats(const float* __restrict__ out) {
    const int c = threadIdx.x;                  // 0..255
    const int rows_per = NPTS / gridDim.x;
    const int r0 = blockIdx.x * rows_per;
    double s = 0.0, s2 = 0.0;
    for (int r = 0; r < rows_per; ++r) {
        float v = out[(r0 + r)*C_OUT + c];
        s += v; s2 += (double)v * v;
    }
    atomicAdd(&g_sum[c], s);
    atomicAdd(&g_sumsq[c], s2);
}

// ---------------- K5b: fold mean/var into scale/shift ----------------
__global__ void k_finstats(const float* __restrict__ bn_g, const float* __restrict__ bn_b) {
    int c = threadIdx.x;
    double inv = 1.0 / (double)NPTS;
    double mean = g_sum[c] * inv;
    double var  = g_sumsq[c] * inv - mean*mean;
    float sc = bn_g[c] * rsqrtf((float)var + EPSV);
    g_scale[c] = sc;
    g_shift[c] = bn_b[c] - (float)mean * sc;
}

// ---------------- K6: apply BN ----------------
__global__ void k_bn(float* __restrict__ out) {
    int idx = blockIdx.x * 256 + threadIdx.x;
    int c = idx & (C_OUT - 1);
    out[idx] = out[idx] * g_scale[c] + g_shift[c];
}

// ---------------- launch ----------------
extern "C" void kernel_launch(void* const* d_in, const int* in_sizes, int n_in,
                              void* d_out, int out_size) {
    const float* rep_pt = (const float*)d_in[0];
    const float* pts    = (const float*)d_in[1];
    const float* fts    = (const float*)d_in[2];
    const float* d1_w   = (const float*)d_in[3];
    const float* d1_b   = (const float*)d_in[4];
    const float* d2_w   = (const float*)d_in[5];
    const float* d2_b   = (const float*)d_in[6];
    const float* cv_w   = (const float*)d_in[7];
    const float* cv_b   = (const float*)d_in[8];
    const float* x1_w   = (const float*)d_in[9];
    const float* x1_b   = (const float*)d_in[10];
    const float* x2_w   = (const float*)d_in[11];
    const float* x2_b   = (const float*)d_in[12];
    const float* dw_w   = (const float*)d_in[13];
    const float* dw_b   = (const float*)d_in[14];
    const float* pw_w   = (const float*)d_in[15];
    const float* bn_g   = (const float*)d_in[16];
    const float* bn_b   = (const float*)d_in[17];
    float* out = (float*)d_out;

    void *pX0, *pX1, *pX2, *pdw;
    cudaGetSymbolAddress(&pX0, g_X0);
    cudaGetSymbolAddress(&pX1, g_X1);
    cudaGetSymbolAddress(&pX2, g_X2);
    cudaGetSymbolAddress(&pdw, g_dw);

    k_zero<<<1, 256>>>();
    k_prep<<<NPTS/PB1, 256>>>(rep_pt, pts, d1_w, d1_b, d2_w, d2_b, cv_w, cv_b);

    // X1 = relu(X0 @ x1_w + x1_b)
    k_gemm<false, true, true><<<dim3(KKDIM/64, NPTS/64), 256>>>(
        (const float*)pX0, x1_w, x1_b, (float*)pX1, NPTS, KKDIM, KKDIM);
    // X2 = X1 @ x2_w + x2_b
    k_gemm<false, false, true><<<dim3(KKDIM/64, NPTS/64), 256>>>(
        (const float*)pX1, x2_w, x2_b, (float*)pX2, NPTS, KKDIM, KKDIM);

    k_xform<<<NPTS/PB4, 192>>>(fts, dw_w, dw_b);

    // out = relu(dw @ pw_w^T)   (pw_w is [N=256, K=384])
    k_gemm<true, true, false><<<dim3(C_OUT/64, NPTS/64), 256>>>(
        (const float*)pdw, pw_w, nullptr, out, NPTS, C_OUT, C_CAT*DMUL);

    k_stats<<<64, 256>>>(out);
    k_finstats<<<1, 256>>>(bn_g, bn_b);
    k_bn<<<(NPTS*C_OUT)/256, 256>>>(out);
}

// round 5
// speedup vs baseline: 1.4575x; 1.4575x over previous
#include <cuda_runtime.h>

#define NB    16
#define PP    1024
#define KNB   16
#define DIMS  3
#define C_IN  128
#define C_MID 64
#define C_OUT 256
#define DMUL  2
#define C_CAT 192
#define NPTS  (NB*PP)        // 16384
#define KKDIM 256            // K*K
#define EPSV  1e-5f

// ---------------- scratch ----------------
__device__ float g_lift[NPTS*KNB*C_MID];
__device__ float g_X0[NPTS*KKDIM];
__device__ float g_X1[NPTS*KKDIM];
__device__ float g_X2[NPTS*KKDIM];
__device__ float g_dw[NPTS*C_CAT*DMUL];
__device__ double g_sum[C_OUT];
__device__ double g_sumsq[C_OUT];
__device__ float g_scale[C_OUT];
__device__ float g_shift[C_OUT];

// ---------------- K0 ----------------
__global__ void k_zero() {
    int t = threadIdx.x;
    if (t < C_OUT) { g_sum[t] = 0.0; g_sumsq[t] = 0.0; }
}

// ---------------- K1: pts_local -> MLP (lifted) + relu'd conv X0 ----------------
#define PB1 4
__global__ __launch_bounds__(256) void k_prep(
        const float* __restrict__ rep_pt, const float* __restrict__ pts,
        const float* __restrict__ d1_w, const float* __restrict__ d1_b,
        const float* __restrict__ d2_w, const float* __restrict__ d2_b,
        const float* __restrict__ cv_w, const float* __restrict__ cv_b) {
    __shared__ float s_pl[PB1*KNB*DIMS];       // pts_local [p][k][d]  (768 B)
    __shared__ float s_h[PB1*KNB][C_MID];      // 16 KB
    __shared__ float s_w[C_MID][C_MID];        // d2_w, 16 KB        -> total ~33 KB
    const int t = threadIdx.x;
    const int pbase = blockIdx.x * PB1;

    for (int idx = t; idx < PB1*KNB*DIMS; idx += 256) {
        int p = idx / (KNB*DIMS);
        int rem = idx % (KNB*DIMS);
        int k = rem / DIMS, d = rem % DIMS;
        int gp = pbase + p;
        s_pl[idx] = pts[(gp*KNB + k)*DIMS + d] - rep_pt[gp*DIMS + d];
    }
    // stage d2_w into smem (4096 floats, float4)
    for (int idx = t*4; idx < C_MID*C_MID; idx += 256*4) {
        float4 v = *reinterpret_cast<const float4*>(&d2_w[idx]);
        *reinterpret_cast<float4*>(&((float*)s_w)[idx]) = v;
    }
    __syncthreads();

    // h = relu(pts_local @ d1_w + d1_b)   (64 rows total, 256 threads)
    {
        int c = t & 63;
        int rg = t >> 6;                       // 0..3, 16 rows each
        float w0 = d1_w[0*C_MID + c], w1 = d1_w[1*C_MID + c], w2 = d1_w[2*C_MID + c];
        float b = d1_b[c];
        #pragma unroll
        for (int r = 0; r < 16; ++r) {
            int row = rg*16 + r;
            const float* pl = &s_pl[row*DIMS];
            float v = b + pl[0]*w0 + pl[1]*w1 + pl[2]*w2;
            s_h[row][c] = fmaxf(v, 0.f);
        }
    }
    __syncthreads();

    // lifted = relu(h @ d2_w + d2_b)  — 4 cols x 4 rows per thread
    {
        int c0 = (t & 15) * 4;                 // 4 consecutive cols
        int rg = t >> 4;                       // 0..15, 4 rows each
        float4 acc[4];
        float4 bia = *reinterpret_cast<const float4*>(&d2_b[c0]);
        #pragma unroll
        for (int r = 0; r < 4; ++r) acc[r] = bia;
        #pragma unroll 8
        for (int kk = 0; kk < C_MID; ++kk) {
            float4 w = *reinterpret_cast<const float4*>(&s_w[kk][c0]);
            #pragma unroll
            for (int r = 0; r < 4; ++r) {
                float h = s_h[rg*4 + r][kk];
                acc[r].x += h * w.x; acc[r].y += h * w.y;
                acc[r].z += h * w.z; acc[r].w += h * w.w;
            }
        }
        #pragma unroll
        for (int r = 0; r < 4; ++r) {
            int row = rg*4 + r;
            float4 v;
            v.x = fmaxf(acc[r].x, 0.f); v.y = fmaxf(acc[r].y, 0.f);
            v.z = fmaxf(acc[r].z, 0.f); v.w = fmaxf(acc[r].w, 0.f);
            *reinterpret_cast<float4*>(&g_lift[(pbase*KNB + row)*C_MID + c0]) = v;
        }
    }

    // X0 = relu(einsum('pkd,odk->po') + cv_b)  (reads only s_pl)
    {
        int o = t;
        float acc[PB1];
        float b = cv_b[o];
        #pragma unroll
        for (int p = 0; p < PB1; ++p) acc[p] = b;
        #pragma unroll
        for (int d = 0; d < DIMS; ++d)
            for (int k = 0; k < KNB; ++k) {
                float w = cv_w[o*(DIMS*KNB) + d*KNB + k];
                #pragma unroll
                for (int p = 0; p < PB1; ++p)
                    acc[p] += s_pl[(p*KNB + k)*DIMS + d] * w;
            }
        #pragma unroll
        for (int p = 0; p < PB1; ++p)
            g_X0[(pbase + p)*KKDIM + o] = fmaxf(acc[p], 0.f);
    }
}

// ---------------- SGEMM v2: 128x128x16 tile, 8x8 microtile, 256 threads ----------------
// A: [M,K] row-major.  B_IS_NK=false: B is [K,N];  true: B is [N,K].
template<bool B_IS_NK, bool RELU, bool USE_BIAS>
__global__ __launch_bounds__(256) void k_gemm128(
        const float* __restrict__ A, const float* __restrict__ B,
        const float* __restrict__ bias, float* __restrict__ C,
        int M, int Nn, int Kd) {
    __shared__ float As[16][128];
    __shared__ float Bs[16][128];
    const int t = threadIdx.x;
    const int tx = t & 15, ty = t >> 4;
    const int rowBase = blockIdx.y * 128;
    const int colBase = blockIdx.x * 128;
    float acc[8][8] = {};

    for (int k0 = 0; k0 < Kd; k0 += 16) {
        #pragma unroll
        for (int pass = 0; pass < 2; ++pass) {     // A tile 128x16, transpose
            int row = (t >> 2) + pass*64;
            int k4 = (t & 3) * 4;
            float4 v = *reinterpret_cast<const float4*>(&A[(rowBase+row)*Kd + k0 + k4]);
            As[k4+0][row] = v.x; As[k4+1][row] = v.y;
            As[k4+2][row] = v.z; As[k4+3][row] = v.w;
        }
        if (!B_IS_NK) {
            #pragma unroll
            for (int pass = 0; pass < 2; ++pass) { // B[K,N] tile 16x128, direct
                int r = (t >> 5) + pass*8;
                int c4 = (t & 31) * 4;
                float4 v = *reinterpret_cast<const float4*>(&B[(k0+r)*Nn + colBase + c4]);
                *reinterpret_cast<float4*>(&Bs[r][c4]) = v;
            }
        } else {
            #pragma unroll
            for (int pass = 0; pass < 2; ++pass) { // B[N,K], transpose
                int n = (t >> 2) + pass*64;
                int k4 = (t & 3) * 4;
                float4 v = *reinterpret_cast<const float4*>(&B[(colBase+n)*Kd + k0 + k4]);
                Bs[k4+0][n] = v.x; Bs[k4+1][n] = v.y;
                Bs[k4+2][n] = v.z; Bs[k4+3][n] = v.w;
            }
        }
        __syncthreads();
        #pragma unroll
        for (int kk = 0; kk < 16; ++kk) {
            float4 a0 = *reinterpret_cast<const float4*>(&As[kk][ty*8]);
            float4 a1 = *reinterpret_cast<const float4*>(&As[kk][ty*8+4]);
            float4 b0 = *reinterpret_cast<const float4*>(&Bs[kk][tx*8]);
            float4 b1 = *reinterpret_cast<const float4*>(&Bs[kk][tx*8+4]);
            float a[8] = {a0.x,a0.y,a0.z,a0.w,a1.x,a1.y,a1.z,a1.w};
            float b[8] = {b0.x,b0.y,b0.z,b0.w,b1.x,b1.y,b1.z,b1.w};
            #pragma unroll
            for (int i = 0; i < 8; ++i)
                #pragma unroll
                for (int j = 0; j < 8; ++j)
                    acc[i][j] += a[i]*b[j];
        }
        __syncthreads();
    }
    float bcol[8];
    #pragma unroll
    for (int j = 0; j < 8; ++j)
        bcol[j] = USE_BIAS ? bias[colBase + tx*8 + j] : 0.f;
    #pragma unroll
    for (int i = 0; i < 8; ++i) {
        int row = rowBase + ty*8 + i;
        float v[8];
        #pragma unroll
        for (int j = 0; j < 8; ++j) {
            float x = acc[i][j] + bcol[j];
            v[j] = RELU ? fmaxf(x, 0.f) : x;
        }
        *reinterpret_cast<float4*>(&C[row*Nn + colBase + tx*8])     = make_float4(v[0],v[1],v[2],v[3]);
        *reinterpret_cast<float4*>(&C[row*Nn + colBase + tx*8 + 4]) = make_float4(v[4],v[5],v[6],v[7]);
    }
}

// ---------------- K4: fts_X = X @ [lifted|fts], then depthwise conv -> g_dw ----------------
#define PB4 4
__global__ __launch_bounds__(192) void k_xform(
        const float* __restrict__ fts,
        const float* __restrict__ dw_w, const float* __restrict__ dw_b) {
    __shared__ float s_X[KKDIM];
    const int t = threadIdx.x;                  // 0..191 = channel c
    const int pbase = blockIdx.x * PB4;
    const int c = t;
    float wreg[DMUL][KNB];
    float breg[DMUL];
    #pragma unroll
    for (int m = 0; m < DMUL; ++m) {
        int jj = c*DMUL + m;
        breg[m] = dw_b[jj];
        #pragma unroll
        for (int k = 0; k < KNB; ++k) wreg[m][k] = dw_w[jj*KNB + k];
    }
    for (int p = 0; p < PB4; ++p) {
        int gp = pbase + p;
        for (int idx = t; idx < KKDIM; idx += 192) s_X[idx] = g_X2[gp*KKDIM + idx];
        __syncthreads();
        float fX[KNB] = {};
        #pragma unroll 4
        for (int j = 0; j < KNB; ++j) {
            float catv = (c < C_MID) ? g_lift[(gp*KNB + j)*C_MID + c]
                                     : fts[(gp*KNB + j)*C_IN + (c - C_MID)];
            #pragma unroll
            for (int k = 0; k < KNB; ++k)
                fX[k] += s_X[k*KNB + j] * catv;
        }
        #pragma unroll
        for (int m = 0; m < DMUL; ++m) {
            float acc = breg[m];
            #pragma unroll
            for (int k = 0; k < KNB; ++k)
                acc += fX[k] * wreg[m][k];
            g_dw[gp*(C_CAT*DMUL) + c*DMUL + m] = acc;
        }
        __syncthreads();
    }
}

// ---------------- K5: per-channel sum / sumsq ----------------
__global__ void k_stats(const float* __restrict__ out) {
    const int c = threadIdx.x;                  // 0..255
    const int rows_per = NPTS / gridDim.x;
    const int r0 = blockIdx.x * rows_per;
    double s = 0.0, s2 = 0.0;
    for (int r = 0; r < rows_per; ++r) {
        float v = out[(r0 + r)*C_OUT + c];
        s += v; s2 += (double)v * v;
    }
    atomicAdd(&g_sum[c], s);
    atomicAdd(&g_sumsq[c], s2);
}

// ---------------- K5b ----------------
__global__ void k_finstats(const float* __restrict__ bn_g, const float* __restrict__ bn_b) {
    int c = threadIdx.x;
    double inv = 1.0 / (double)NPTS;
    double mean = g_sum[c] * inv;
    double var  = g_sumsq[c] * inv - mean*mean;
    float sc = bn_g[c] * rsqrtf((float)var + EPSV);
    g_scale[c] = sc;
    g_shift[c] = bn_b[c] - (float)mean * sc;
}

// ---------------- K6: apply BN (float4) ----------------
__global__ void k_bn(float* __restrict__ out) {
    int idx = (blockIdx.x * 256 + threadIdx.x) * 4;
    int c = idx & (C_OUT - 1);
    float4 v = *reinterpret_cast<float4*>(&out[idx]);
    v.x = v.x * g_scale[c]   + g_shift[c];
    v.y = v.y * g_scale[c+1] + g_shift[c+1];
    v.z = v.z * g_scale[c+2] + g_shift[c+2];
    v.w = v.w * g_scale[c+3] + g_shift[c+3];
    *reinterpret_cast<float4*>(&out[idx]) = v;
}

// ---------------- launch ----------------
extern "C" void kernel_launch(void* const* d_in, const int* in_sizes, int n_in,
                              void* d_out, int out_size) {
    const float* rep_pt = (const float*)d_in[0];
    const float* pts    = (const float*)d_in[1];
    const float* fts    = (const float*)d_in[2];
    const float* d1_w   = (const float*)d_in[3];
    const float* d1_b   = (const float*)d_in[4];
    const float* d2_w   = (const float*)d_in[5];
    const float* d2_b   = (const float*)d_in[6];
    const float* cv_w   = (const float*)d_in[7];
    const float* cv_b   = (const float*)d_in[8];
    const float* x1_w   = (const float*)d_in[9];
    const float* x1_b   = (const float*)d_in[10];
    const float* x2_w   = (const float*)d_in[11];
    const float* x2_b   = (const float*)d_in[12];
    const float* dw_w   = (const float*)d_in[13];
    const float* dw_b   = (const float*)d_in[14];
    const float* pw_w   = (const float*)d_in[15];
    const float* bn_g   = (const float*)d_in[16];
    const float* bn_b   = (const float*)d_in[17];
    float* out = (float*)d_out;

    void *pX0, *pX1, *pX2, *pdw;
    cudaGetSymbolAddress(&pX0, g_X0);
    cudaGetSymbolAddress(&pX1, g_X1);
    cudaGetSymbolAddress(&pX2, g_X2);
    cudaGetSymbolAddress(&pdw, g_dw);

    k_zero<<<1, 256>>>();
    k_prep<<<NPTS/PB1, 256>>>(rep_pt, pts, d1_w, d1_b, d2_w, d2_b, cv_w, cv_b);

    // X1 = relu(X0 @ x1_w + x1_b)
    k_gemm128<false, true, true><<<dim3(KKDIM/128, NPTS/128), 256>>>(
        (const float*)pX0, x1_w, x1_b, (float*)pX1, NPTS, KKDIM, KKDIM);
    // X2 = X1 @ x2_w + x2_b
    k_gemm128<false, false, true><<<dim3(KKDIM/128, NPTS/128), 256>>>(
        (const float*)pX1, x2_w, x2_b, (float*)pX2, NPTS, KKDIM, KKDIM);

    k_xform<<<NPTS/PB4, 192>>>(fts, dw_w, dw_b);

    // out = relu(dw @ pw_w^T)   (pw_w is [N=256, K=384])
    k_gemm128<true, true, false><<<dim3(C_OUT/128, NPTS/128), 256>>>(
        (const float*)pdw, pw_w, nullptr, out, NPTS, C_OUT, C_CAT*DMUL);

    k_stats<<<256, 256>>>(out);
    k_finstats<<<1, 256>>>(bn_g, bn_b);
    k_bn<<<(NPTS*C_OUT)/1024, 256>>>(out);
}

// round 7
// speedup vs baseline: 1.9429x; 1.3331x over previous
#include <cuda_runtime.h>
#include <cuda_bf16.h>
#include <cstdint>

#define NB    16
#define PP    1024
#define KNB   16
#define DIMS  3
#define C_IN  128
#define C_MID 64
#define C_OUT 256
#define DMUL  2
#define C_CAT 192
#define NPTS  (NB*PP)        // 16384
#define KKDIM 256            // K*K
#define EPSV  1e-5f

// ---------------- scratch ----------------
__device__ float g_h[NPTS*KNB*C_MID];        // stage-1 MLP output
__device__ float g_lift[NPTS*KNB*C_MID];
__device__ float g_X0[NPTS*KKDIM];
__device__ float g_X1[NPTS*KKDIM];
__device__ float g_X2[NPTS*KKDIM];
__device__ float g_dw[NPTS*C_CAT*DMUL];
__device__ float g_wt1[KKDIM*KKDIM];         // x1_w transposed [N,K]
__device__ float g_wt2[KKDIM*KKDIM];
__device__ float g_wtd[C_MID*C_MID];         // d2_w transposed
__device__ double g_sum[C_OUT];
__device__ double g_sumsq[C_OUT];
__device__ float g_scale[C_OUT];
__device__ float g_shift[C_OUT];

// ---------------- K0 ----------------
__global__ void k_zero() {
    int t = threadIdx.x;
    if (t < C_OUT) { g_sum[t] = 0.0; g_sumsq[t] = 0.0; }
}

// ---------------- transpose: src[R][C] -> dst[C][R] ----------------
__global__ void k_transp(const float* __restrict__ src, float* __restrict__ dst,
                         int R, int C) {
    __shared__ float s[32][33];
    int bx = blockIdx.x, by = blockIdx.y;
    int tx = threadIdx.x & 31, ty = threadIdx.x >> 5;
    #pragma unroll
    for (int i = 0; i < 4; ++i) {
        int r = by * 32 + ty + i * 8;
        s[ty + i * 8][tx] = src[r * C + bx * 32 + tx];
    }
    __syncthreads();
    #pragma unroll
    for (int i = 0; i < 4; ++i) {
        int r = bx * 32 + ty + i * 8;
        dst[r * R + by * 32 + tx] = s[tx][ty + i * 8];
    }
}

// ---------------- K1: pts_local -> h (g_h) + relu'd conv X0 ----------------
#define PB1 8
__global__ __launch_bounds__(256) void k_prep(
        const float* __restrict__ rep_pt, const float* __restrict__ pts,
        const float* __restrict__ d1_w, const float* __restrict__ d1_b,
        const float* __restrict__ cv_w, const float* __restrict__ cv_b) {
    __shared__ float s_pl[PB1*KNB*DIMS];
    const int t = threadIdx.x;
    const int pbase = blockIdx.x * PB1;

    for (int idx = t; idx < PB1*KNB*DIMS; idx += 256) {
        int p = idx / (KNB*DIMS);
        int rem = idx % (KNB*DIMS);
        int k = rem / DIMS, d = rem % DIMS;
        int gp = pbase + p;
        s_pl[idx] = pts[(gp*KNB + k)*DIMS + d] - rep_pt[gp*DIMS + d];
    }
    __syncthreads();

    // h = relu(pts_local @ d1_w + d1_b) -> g_h  (128 rows)
    {
        int c = t & 63;
        int rg = t >> 6;                       // 0..3, 32 rows each
        float w0 = d1_w[0*C_MID + c], w1 = d1_w[1*C_MID + c], w2 = d1_w[2*C_MID + c];
        float b = d1_b[c];
        #pragma unroll 8
        for (int r = 0; r < 32; ++r) {
            int row = rg*32 + r;
            const float* pl = &s_pl[row*DIMS];
            float v = b + pl[0]*w0 + pl[1]*w1 + pl[2]*w2;
            g_h[(size_t)(pbase*KNB + row)*C_MID + c] = fmaxf(v, 0.f);
        }
    }

    // X0 = relu(einsum('pkd,odk->po') + cv_b)
    {
        int o = t;
        float acc[PB1];
        float b = cv_b[o];
        #pragma unroll
        for (int p = 0; p < PB1; ++p) acc[p] = b;
        #pragma unroll
        for (int d = 0; d < DIMS; ++d)
            for (int k = 0; k < KNB; ++k) {
                float w = cv_w[o*(DIMS*KNB) + d*KNB + k];
                #pragma unroll
                for (int p = 0; p < PB1; ++p)
                    acc[p] += s_pl[(p*KNB + k)*DIMS + d] * w;
            }
        #pragma unroll
        for (int p = 0; p < PB1; ++p)
            g_X0[(size_t)(pbase + p)*KKDIM + o] = fmaxf(acc[p], 0.f);
    }
}

// ---------------- bf16x3 tensor-core GEMM (mma.sync, base ISA) ----------------
// C[M, Nn] = act(A[M, KD] @ Bt[Nn, KD]^T (+bias))
// Block tile: 128 x BN, BK=32. 8 warps = 4(m) x 2(n); warp tile 32 x BN/2.
__device__ __forceinline__ void mma16816(float* c, const uint32_t* a,
                                         uint32_t b0, uint32_t b1) {
    asm volatile(
        "mma.sync.aligned.m16n8k16.row.col.f32.bf16.bf16.f32 "
        "{%0,%1,%2,%3}, {%4,%5,%6,%7}, {%8,%9}, {%0,%1,%2,%3};"
        : "+f"(c[0]), "+f"(c[1]), "+f"(c[2]), "+f"(c[3])
        : "r"(a[0]), "r"(a[1]), "r"(a[2]), "r"(a[3]), "r"(b0), "r"(b1));
}

#define SPAD 36   // smem row stride (bf16 elems) to spread banks

template<int BN, int KD, bool RELU, bool USE_BIAS>
__global__ __launch_bounds__(256) void k_mma(
        const float* __restrict__ A, const float* __restrict__ Bt,
        const float* __restrict__ bias, float* __restrict__ C, int Nn) {
    __shared__ __nv_bfloat16 sA[2][128][SPAD];
    __shared__ __nv_bfloat16 sB[2][BN][SPAD];
    constexpr int NT = BN / 16;                // n-tiles per warp
    constexpr int KCH = KD / 32;

    const int t = threadIdx.x;
    const int wid = t >> 5, lid = t & 31;
    const int g = lid >> 2, tg = lid & 3;
    const int wm = wid & 3, wn = wid >> 2;
    const long rowBase = (long)blockIdx.y * 128;
    const int nBase = blockIdx.x * BN;

    float acc[2][NT][4];
    #pragma unroll
    for (int mt = 0; mt < 2; ++mt)
        #pragma unroll
        for (int nt = 0; nt < NT; ++nt)
            #pragma unroll
            for (int i = 0; i < 4; ++i) acc[mt][nt][i] = 0.f;

    for (int ch = 0; ch < KCH; ++ch) {
        // ---- load + split A tile (128 x 32 fp32) ----
        #pragma unroll
        for (int i = 0; i < 4; ++i) {
            int idx = i * 1024 + t * 4;
            int row = idx >> 5, col = idx & 31;
            float4 v = *reinterpret_cast<const float4*>(
                &A[(rowBase + row) * KD + ch * 32 + col]);
            __nv_bfloat162 h01 = __float22bfloat162_rn(make_float2(v.x, v.y));
            __nv_bfloat162 h23 = __float22bfloat162_rn(make_float2(v.z, v.w));
            float2 hf01 = __bfloat1622float2(h01);
            float2 hf23 = __bfloat1622float2(h23);
            __nv_bfloat162 l01 = __float22bfloat162_rn(
                make_float2(v.x - hf01.x, v.y - hf01.y));
            __nv_bfloat162 l23 = __float22bfloat162_rn(
                make_float2(v.z - hf23.x, v.w - hf23.y));
            *reinterpret_cast<__nv_bfloat162*>(&sA[0][row][col])     = h01;
            *reinterpret_cast<__nv_bfloat162*>(&sA[0][row][col + 2]) = h23;
            *reinterpret_cast<__nv_bfloat162*>(&sA[1][row][col])     = l01;
            *reinterpret_cast<__nv_bfloat162*>(&sA[1][row][col + 2]) = l23;
        }
        // ---- load + split B tile (BN x 32 fp32) ----
        #pragma unroll
        for (int i = 0; i < BN / 32; ++i) {
            int idx = i * 1024 + t * 4;
            int row = idx >> 5, col = idx & 31;
            float4 v = *reinterpret_cast<const float4*>(
                &Bt[(long)(nBase + row) * KD + ch * 32 + col]);
            __nv_bfloat162 h01 = __float22bfloat162_rn(make_float2(v.x, v.y));
            __nv_bfloat162 h23 = __float22bfloat162_rn(make_float2(v.z, v.w));
            float2 hf01 = __bfloat1622float2(h01);
            float2 hf23 = __bfloat1622float2(h23);
            __nv_bfloat162 l01 = __float22bfloat162_rn(
                make_float2(v.x - hf01.x, v.y - hf01.y));
            __nv_bfloat162 l23 = __float22bfloat162_rn(
                make_float2(v.z - hf23.x, v.w - hf23.y));
            *reinterpret_cast<__nv_bfloat162*>(&sB[0][row][col])     = h01;
            *reinterpret_cast<__nv_bfloat162*>(&sB[0][row][col + 2]) = h23;
            *reinterpret_cast<__nv_bfloat162*>(&sB[1][row][col])     = l01;
            *reinterpret_cast<__nv_bfloat162*>(&sB[1][row][col + 2]) = l23;
        }
        __syncthreads();

        #pragma unroll
        for (int ks = 0; ks < 2; ++ks) {
            int kb = ks * 16 + 2 * tg;
            uint32_t ah[2][4], al[2][4];
            #pragma unroll
            for (int mt = 0; mt < 2; ++mt) {
                int r0 = wm * 32 + mt * 16 + g;
                ah[mt][0] = *reinterpret_cast<const uint32_t*>(&sA[0][r0][kb]);
                ah[mt][1] = *reinterpret_cast<const uint32_t*>(&sA[0][r0 + 8][kb]);
                ah[mt][2] = *reinterpret_cast<const uint32_t*>(&sA[0][r0][kb + 8]);
                ah[mt][3] = *reinterpret_cast<const uint32_t*>(&sA[0][r0 + 8][kb + 8]);
                al[mt][0] = *reinterpret_cast<const uint32_t*>(&sA[1][r0][kb]);
                al[mt][1] = *reinterpret_cast<const uint32_t*>(&sA[1][r0 + 8][kb]);
                al[mt][2] = *reinterpret_cast<const uint32_t*>(&sA[1][r0][kb + 8]);
                al[mt][3] = *reinterpret_cast<const uint32_t*>(&sA[1][r0 + 8][kb + 8]);
            }
            #pragma unroll
            for (int nt = 0; nt < NT; ++nt) {
                int n = wn * (BN / 2) + nt * 8 + g;
                uint32_t bh0 = *reinterpret_cast<const uint32_t*>(&sB[0][n][kb]);
                uint32_t bh1 = *reinterpret_cast<const uint32_t*>(&sB[0][n][kb + 8]);
                uint32_t bl0 = *reinterpret_cast<const uint32_t*>(&sB[1][n][kb]);
                uint32_t bl1 = *reinterpret_cast<const uint32_t*>(&sB[1][n][kb + 8]);
                #pragma unroll
                for (int mt = 0; mt < 2; ++mt) {
                    mma16816(acc[mt][nt], ah[mt], bh0, bh1);
                    mma16816(acc[mt][nt], ah[mt], bl0, bl1);
                    mma16816(acc[mt][nt], al[mt], bh0, bh1);
                }
            }
        }
        __syncthreads();
    }

    // ---- epilogue ----
    #pragma unroll
    for (int mt = 0; mt < 2; ++mt) {
        long row0 = rowBase + wm * 32 + mt * 16 + g;
        #pragma unroll
        for (int nt = 0; nt < NT; ++nt) {
            int col = nBase + wn * (BN / 2) + nt * 8 + 2 * tg;
            float b0 = USE_BIAS ? bias[col]     : 0.f;
            float b1 = USE_BIAS ? bias[col + 1] : 0.f;
            float v0 = acc[mt][nt][0] + b0, v1 = acc[mt][nt][1] + b1;
            float v2 = acc[mt][nt][2] + b0, v3 = acc[mt][nt][3] + b1;
            if (RELU) {
                v0 = fmaxf(v0, 0.f); v1 = fmaxf(v1, 0.f);
                v2 = fmaxf(v2, 0.f); v3 = fmaxf(v3, 0.f);
            }
            *reinterpret_cast<float2*>(&C[row0 * Nn + col])       = make_float2(v0, v1);
            *reinterpret_cast<float2*>(&C[(row0 + 8) * Nn + col]) = make_float2(v2, v3);
        }
    }
}

// ---------------- K4: fts_X = X @ [lifted|fts], then depthwise conv -> g_dw ----------------
#define PB4 4
__global__ __launch_bounds__(192) void k_xform(
        const float* __restrict__ fts,
        const float* __restrict__ dw_w, const float* __restrict__ dw_b) {
    __shared__ float s_X[KKDIM];
    const int t = threadIdx.x;                  // 0..191 = channel c
    const int pbase = blockIdx.x * PB4;
    const int c = t;
    float wreg[DMUL][KNB];
    float breg[DMUL];
    #pragma unroll
    for (int m = 0; m < DMUL; ++m) {
        int jj = c*DMUL + m;
        breg[m] = dw_b[jj];
        #pragma unroll
        for (int k = 0; k < KNB; ++k) wreg[m][k] = dw_w[jj*KNB + k];
    }
    for (int p = 0; p < PB4; ++p) {
        int gp = pbase + p;
        for (int idx = t; idx < KKDIM; idx += 192) s_X[idx] = g_X2[(size_t)gp*KKDIM + idx];
        __syncthreads();
        float fX[KNB] = {};
        #pragma unroll 4
        for (int j = 0; j < KNB; ++j) {
            float catv = (c < C_MID) ? g_lift[(size_t)(gp*KNB + j)*C_MID + c]
                                     : fts[(size_t)(gp*KNB + j)*C_IN + (c - C_MID)];
            #pragma unroll
            for (int k = 0; k < KNB; ++k)
                fX[k] += s_X[k*KNB + j] * catv;
        }
        #pragma unroll
        for (int m = 0; m < DMUL; ++m) {
            float acc = breg[m];
            #pragma unroll
            for (int k = 0; k < KNB; ++k)
                acc += fX[k] * wreg[m][k];
            g_dw[(size_t)gp*(C_CAT*DMUL) + c*DMUL + m] = acc;
        }
        __syncthreads();
    }
}

// ---------------- K5: per-channel sum / sumsq ----------------
__global__ void k_stats(const float* __restrict__ out) {
    const int c = threadIdx.x;
    const int rows_per = NPTS / gridDim.x;
    const int r0 = blockIdx.x * rows_per;
    double s = 0.0, s2 = 0.0;
    for (int r = 0; r < rows_per; ++r) {
        float v = out[(size_t)(r0 + r)*C_OUT + c];
        s += v; s2 += (double)v * v;
    }
    atomicAdd(&g_sum[c], s);
    atomicAdd(&g_sumsq[c], s2);
}

// ---------------- K5b ----------------
__global__ void k_finstats(const float* __restrict__ bn_g, const float* __restrict__ bn_b) {
    int c = threadIdx.x;
    double inv = 1.0 / (double)NPTS;
    double mean = g_sum[c] * inv;
    double var  = g_sumsq[c] * inv - mean*mean;
    float sc = bn_g[c] * rsqrtf((float)var + EPSV);
    g_scale[c] = sc;
    g_shift[c] = bn_b[c] - (float)mean * sc;
}

// ---------------- K6: apply BN (float4) ----------------
__global__ void k_bn(float* __restrict__ out) {
    int idx = (blockIdx.x * 256 + threadIdx.x) * 4;
    int c = idx & (C_OUT - 1);
    float4 v = *reinterpret_cast<float4*>(&out[idx]);
    v.x = v.x * g_scale[c]   + g_shift[c];
    v.y = v.y * g_scale[c+1] + g_shift[c+1];
    v.z = v.z * g_scale[c+2] + g_shift[c+2];
    v.w = v.w * g_scale[c+3] + g_shift[c+3];
    *reinterpret_cast<float4*>(&out[idx]) = v;
}

// ---------------- launch ----------------
extern "C" void kernel_launch(void* const* d_in, const int* in_sizes, int n_in,
                              void* d_out, int out_size) {
    const float* rep_pt = (const float*)d_in[0];
    const float* pts    = (const float*)d_in[1];
    const float* fts    = (const float*)d_in[2];
    const float* d1_w   = (const float*)d_in[3];
    const float* d1_b   = (const float*)d_in[4];
    const float* d2_w   = (const float*)d_in[5];
    const float* d2_b   = (const float*)d_in[6];
    const float* cv_w   = (const float*)d_in[7];
    const float* cv_b   = (const float*)d_in[8];
    const float* x1_w   = (const float*)d_in[9];
    const float* x1_b   = (const float*)d_in[10];
    const float* x2_w   = (const float*)d_in[11];
    const float* x2_b   = (const float*)d_in[12];
    const float* dw_w   = (const float*)d_in[13];
    const float* dw_b   = (const float*)d_in[14];
    const float* pw_w   = (const float*)d_in[15];
    const float* bn_g   = (const float*)d_in[16];
    const float* bn_b   = (const float*)d_in[17];
    float* out = (float*)d_out;

    void *ph, *pX0, *pX1, *pX2, *pdw, *pwt1, *pwt2, *pwtd, *plift;
    cudaGetSymbolAddress(&ph,   g_h);
    cudaGetSymbolAddress(&pX0,  g_X0);
    cudaGetSymbolAddress(&pX1,  g_X1);
    cudaGetSymbolAddress(&pX2,  g_X2);
    cudaGetSymbolAddress(&pdw,  g_dw);
    cudaGetSymbolAddress(&pwt1, g_wt1);
    cudaGetSymbolAddress(&pwt2, g_wt2);
    cudaGetSymbolAddress(&pwtd, g_wtd);
    cudaGetSymbolAddress(&plift, g_lift);

    k_zero<<<1, 256>>>();
    k_transp<<<dim3(KKDIM/32, KKDIM/32), 256>>>(x1_w, (float*)pwt1, KKDIM, KKDIM);
    k_transp<<<dim3(KKDIM/32, KKDIM/32), 256>>>(x2_w, (float*)pwt2, KKDIM, KKDIM);
    k_transp<<<dim3(C_MID/32, C_MID/32), 256>>>(d2_w, (float*)pwtd, C_MID, C_MID);

    k_prep<<<NPTS/PB1, 256>>>(rep_pt, pts, d1_w, d1_b, cv_w, cv_b);

    // lifted = relu(h @ d2_w + d2_b):  M=262144, N=64, K=64
    k_mma<64, 64, true, true><<<dim3(1, (NPTS*KNB)/128), 256>>>(
        (const float*)ph, (const float*)pwtd, d2_b, (float*)plift, C_MID);

    // X1 = relu(X0 @ x1_w + x1_b):  M=16384, N=256, K=256
    k_mma<128, 256, true, true><<<dim3(2, NPTS/128), 256>>>(
        (const float*)pX0, (const float*)pwt1, x1_b, (float*)pX1, KKDIM);
    // X2 = X1 @ x2_w + x2_b
    k_mma<128, 256, false, true><<<dim3(2, NPTS/128), 256>>>(
        (const float*)pX1, (const float*)pwt2, x2_b, (float*)pX2, KKDIM);

    k_xform<<<NPTS/PB4, 192>>>(fts, dw_w, dw_b);

    // out = relu(dw @ pw_w^T):  M=16384, N=256, K=384  (pw_w already [N,K])
    k_mma<128, 384, true, false><<<dim3(2, NPTS/128), 256>>>(
        (const float*)pdw, pw_w, nullptr, out, C_OUT);

    k_stats<<<256, 256>>>(out);
    k_finstats<<<1, 256>>>(bn_g, bn_b);
    k_bn<<<(NPTS*C_OUT)/1024, 256>>>(out);
}

// round 10
// speedup vs baseline: 2.2285x; 1.1470x over previous
#include <cuda_runtime.h>
#include <cuda_bf16.h>
#include <cstdint>

#define NB    16
#define PP    1024
#define KNB   16
#define DIMS  3
#define C_IN  128
#define C_MID 64
#define C_OUT 256
#define DMUL  2
#define C_CAT 192
#define NPTS  (NB*PP)        // 16384
#define KKDIM 256            // K*K
#define EPSV  1e-5f

// ---------------- scratch ----------------
__device__ float g_lift[NPTS*KNB*C_MID];
__device__ float g_X0[NPTS*KKDIM];
__device__ float g_X1[NPTS*KKDIM];
__device__ float g_X2[NPTS*KKDIM];
__device__ float g_dw[NPTS*C_CAT*DMUL];
__device__ float g_wt1[KKDIM*KKDIM];         // x1_w transposed [N,K]
__device__ float g_wt2[KKDIM*KKDIM];
__device__ float g_wtd[C_MID*C_MID];         // d2_w transposed
__device__ double g_sum[C_OUT];
__device__ double g_sumsq[C_OUT];
__device__ float g_scale[C_OUT];
__device__ float g_shift[C_OUT];

// ---------------- K0 ----------------
__global__ void k_zero() {
    int t = threadIdx.x;
    if (t < C_OUT) { g_sum[t] = 0.0; g_sumsq[t] = 0.0; }
}

// ---------------- transpose: src[R][C] -> dst[C][R] ----------------
__global__ void k_transp(const float* __restrict__ src, float* __restrict__ dst,
                         int R, int C) {
    __shared__ float s[32][33];
    int bx = blockIdx.x, by = blockIdx.y;
    int tx = threadIdx.x & 31, ty = threadIdx.x >> 5;
    #pragma unroll
    for (int i = 0; i < 4; ++i) {
        int r = by * 32 + ty + i * 8;
        s[ty + i * 8][tx] = src[r * C + bx * 32 + tx];
    }
    __syncthreads();
    #pragma unroll
    for (int i = 0; i < 4; ++i) {
        int r = bx * 32 + ty + i * 8;
        dst[r * R + by * 32 + tx] = s[tx][ty + i * 8];
    }
}

__device__ __forceinline__ void mma16816(float* c, const uint32_t* a,
                                         uint32_t b0, uint32_t b1) {
    asm volatile(
        "mma.sync.aligned.m16n8k16.row.col.f32.bf16.bf16.f32 "
        "{%0,%1,%2,%3}, {%4,%5,%6,%7}, {%8,%9}, {%0,%1,%2,%3};"
        : "+f"(c[0]), "+f"(c[1]), "+f"(c[2]), "+f"(c[3])
        : "r"(a[0]), "r"(a[1]), "r"(a[2]), "r"(a[3]), "r"(b0), "r"(b1));
}

__device__ __forceinline__ void split_bf16(float4 v, __nv_bfloat162& h01,
                                           __nv_bfloat162& h23,
                                           __nv_bfloat162& l01,
                                           __nv_bfloat162& l23) {
    h01 = __float22bfloat162_rn(make_float2(v.x, v.y));
    h23 = __float22bfloat162_rn(make_float2(v.z, v.w));
    float2 f01 = __bfloat1622float2(h01);
    float2 f23 = __bfloat1622float2(h23);
    l01 = __float22bfloat162_rn(make_float2(v.x - f01.x, v.y - f01.y));
    l23 = __float22bfloat162_rn(make_float2(v.z - f23.x, v.w - f23.y));
}

// ---------------- K1 fused: pts_local -> d1 MLP -> d2 MMA -> g_lift, + X0 ----------------
// 1 CTA = 8 points = 128 rows (one MMA tile). d2 GEMM done in-place via bf16x3 mma.
#define PB1 8
#define PSTR 68   // smem col stride (bf16 elems) for A/B planes
#define SPL_BYTES 1536                      // PB1*KNB*DIMS floats = 384*4
__global__ __launch_bounds__(256) void k_prep(
        const float* __restrict__ rep_pt, const float* __restrict__ pts,
        const float* __restrict__ d1_w, const float* __restrict__ d1_b,
        const float* __restrict__ d2wt, const float* __restrict__ d2_b,
        const float* __restrict__ cv_w, const float* __restrict__ cv_b) {
    extern __shared__ char smem[];
    float* s_pl = (float*)smem;                                        // 1536 B
    __nv_bfloat16* sA = (__nv_bfloat16*)(smem + SPL_BYTES);            // [2][128][PSTR]
    __nv_bfloat16* sB = (__nv_bfloat16*)(smem + SPL_BYTES + 2*128*PSTR*2); // [2][64][PSTR]
#define SA(pl, r, cc) sA[((pl)*128 + (r))*PSTR + (cc)]
#define SB(pl, r, cc) sB[((pl)*64 + (r))*PSTR + (cc)]

    const int t = threadIdx.x;
    const int pbase = blockIdx.x * PB1;
    const int wid = t >> 5, lid = t & 31;
    const int g = lid >> 2, tg = lid & 3;
    const int wm = wid & 3, wn = wid >> 2;

    for (int idx = t; idx < PB1*KNB*DIMS; idx += 256) {
        int p = idx / (KNB*DIMS);
        int rem = idx % (KNB*DIMS);
        int k = rem / DIMS, d = rem % DIMS;
        int gp = pbase + p;
        s_pl[idx] = pts[(gp*KNB + k)*DIMS + d] - rep_pt[gp*DIMS + d];
    }
    // stage d2wt [64][64] as bf16 hi/lo
    for (int idx = t * 4; idx < C_MID*C_MID; idx += 1024) {
        int row = idx >> 6, col = idx & 63;
        float4 v = *reinterpret_cast<const float4*>(&d2wt[idx]);
        __nv_bfloat162 h01, h23, l01, l23;
        split_bf16(v, h01, h23, l01, l23);
        *reinterpret_cast<__nv_bfloat162*>(&SB(0, row, col))     = h01;
        *reinterpret_cast<__nv_bfloat162*>(&SB(0, row, col + 2)) = h23;
        *reinterpret_cast<__nv_bfloat162*>(&SB(1, row, col))     = l01;
        *reinterpret_cast<__nv_bfloat162*>(&SB(1, row, col + 2)) = l23;
    }
    __syncthreads();

    // h = relu(pts_local @ d1_w + d1_b) -> sA hi/lo (2 cols x 16 rows per thread)
    {
        int c0 = (t & 31) * 2;
        int rg = t >> 5;                           // 0..7, 16 rows each
        float w00 = d1_w[0*C_MID + c0], w01 = d1_w[0*C_MID + c0 + 1];
        float w10 = d1_w[1*C_MID + c0], w11 = d1_w[1*C_MID + c0 + 1];
        float w20 = d1_w[2*C_MID + c0], w21 = d1_w[2*C_MID + c0 + 1];
        float b0 = d1_b[c0], b1 = d1_b[c0 + 1];
        #pragma unroll
        for (int r = 0; r < 16; ++r) {
            int row = rg * 16 + r;
            const float* pl = &s_pl[row * DIMS];
            float v0 = fmaxf(b0 + pl[0]*w00 + pl[1]*w10 + pl[2]*w20, 0.f);
            float v1 = fmaxf(b1 + pl[0]*w01 + pl[1]*w11 + pl[2]*w21, 0.f);
            __nv_bfloat162 h = __float22bfloat162_rn(make_float2(v0, v1));
            float2 hf = __bfloat1622float2(h);
            __nv_bfloat162 l = __float22bfloat162_rn(make_float2(v0 - hf.x, v1 - hf.y));
            *reinterpret_cast<__nv_bfloat162*>(&SA(0, row, c0)) = h;
            *reinterpret_cast<__nv_bfloat162*>(&SA(1, row, c0)) = l;
        }
    }
    __syncthreads();

    // d2 MMA: 128x64, K=64, bf16x3.  8 warps = 4m x 2n; warp tile 32 x 32.
    {
        float acc[2][4][4];
        #pragma unroll
        for (int mt = 0; mt < 2; ++mt)
            #pragma unroll
            for (int nt = 0; nt < 4; ++nt)
                #pragma unroll
                for (int i = 0; i < 4; ++i) acc[mt][nt][i] = 0.f;

        #pragma unroll
        for (int ks = 0; ks < 4; ++ks) {
            int kb = ks * 16 + 2 * tg;
            uint32_t ah[2][4], al[2][4];
            #pragma unroll
            for (int mt = 0; mt < 2; ++mt) {
                int r0 = wm * 32 + mt * 16 + g;
                ah[mt][0] = *reinterpret_cast<const uint32_t*>(&SA(0, r0, kb));
                ah[mt][1] = *reinterpret_cast<const uint32_t*>(&SA(0, r0 + 8, kb));
                ah[mt][2] = *reinterpret_cast<const uint32_t*>(&SA(0, r0, kb + 8));
                ah[mt][3] = *reinterpret_cast<const uint32_t*>(&SA(0, r0 + 8, kb + 8));
                al[mt][0] = *reinterpret_cast<const uint32_t*>(&SA(1, r0, kb));
                al[mt][1] = *reinterpret_cast<const uint32_t*>(&SA(1, r0 + 8, kb));
                al[mt][2] = *reinterpret_cast<const uint32_t*>(&SA(1, r0, kb + 8));
                al[mt][3] = *reinterpret_cast<const uint32_t*>(&SA(1, r0 + 8, kb + 8));
            }
            #pragma unroll
            for (int nt = 0; nt < 4; ++nt) {
                int n = wn * 32 + nt * 8 + g;
                uint32_t bh0 = *reinterpret_cast<const uint32_t*>(&SB(0, n, kb));
                uint32_t bh1 = *reinterpret_cast<const uint32_t*>(&SB(0, n, kb + 8));
                uint32_t bl0 = *reinterpret_cast<const uint32_t*>(&SB(1, n, kb));
                uint32_t bl1 = *reinterpret_cast<const uint32_t*>(&SB(1, n, kb + 8));
                #pragma unroll
                for (int mt = 0; mt < 2; ++mt) {
                    mma16816(acc[mt][nt], ah[mt], bh0, bh1);
                    mma16816(acc[mt][nt], ah[mt], bl0, bl1);
                    mma16816(acc[mt][nt], al[mt], bh0, bh1);
                }
            }
        }
        // epilogue: relu(acc + d2_b) -> g_lift
        #pragma unroll
        for (int mt = 0; mt < 2; ++mt) {
            int row0 = wm * 32 + mt * 16 + g;
            #pragma unroll
            for (int nt = 0; nt < 4; ++nt) {
                int col = wn * 32 + nt * 8 + 2 * tg;
                float b0 = d2_b[col], b1 = d2_b[col + 1];
                float v0 = fmaxf(acc[mt][nt][0] + b0, 0.f);
                float v1 = fmaxf(acc[mt][nt][1] + b1, 0.f);
                float v2 = fmaxf(acc[mt][nt][2] + b0, 0.f);
                float v3 = fmaxf(acc[mt][nt][3] + b1, 0.f);
                *reinterpret_cast<float2*>(
                    &g_lift[(size_t)(pbase*KNB + row0)*C_MID + col]) = make_float2(v0, v1);
                *reinterpret_cast<float2*>(
                    &g_lift[(size_t)(pbase*KNB + row0 + 8)*C_MID + col]) = make_float2(v2, v3);
            }
        }
    }

    // X0 = relu(einsum('pkd,odk->po') + cv_b)  (reads only s_pl)
    {
        int o = t;
        float acc[PB1];
        float b = cv_b[o];
        #pragma unroll
        for (int p = 0; p < PB1; ++p) acc[p] = b;
        #pragma unroll
        for (int d = 0; d < DIMS; ++d)
            for (int k = 0; k < KNB; ++k) {
                float w = cv_w[o*(DIMS*KNB) + d*KNB + k];
                #pragma unroll
                for (int p = 0; p < PB1; ++p)
                    acc[p] += s_pl[(p*KNB + k)*DIMS + d] * w;
            }
        #pragma unroll
        for (int p = 0; p < PB1; ++p)
            g_X0[(size_t)(pbase + p)*KKDIM + o] = fmaxf(acc[p], 0.f);
    }
#undef SA
#undef SB
}

// ---------------- bf16x3 tensor-core GEMM (mma.sync) ----------------
#define SPAD 36
template<int BN, int KD, bool RELU, bool USE_BIAS>
__global__ __launch_bounds__(256) void k_mma(
        const float* __restrict__ A, const float* __restrict__ Bt,
        const float* __restrict__ bias, float* __restrict__ C, int Nn) {
    __shared__ __nv_bfloat16 sA[2][128][SPAD];
    __shared__ __nv_bfloat16 sB[2][BN][SPAD];
    constexpr int NT = BN / 16;
    constexpr int KCH = KD / 32;

    const int t = threadIdx.x;
    const int wid = t >> 5, lid = t & 31;
    const int g = lid >> 2, tg = lid & 3;
    const int wm = wid & 3, wn = wid >> 2;
    const long rowBase = (long)blockIdx.y * 128;
    const int nBase = blockIdx.x * BN;

    float acc[2][NT][4];
    #pragma unroll
    for (int mt = 0; mt < 2; ++mt)
        #pragma unroll
        for (int nt = 0; nt < NT; ++nt)
            #pragma unroll
            for (int i = 0; i < 4; ++i) acc[mt][nt][i] = 0.f;

    for (int ch = 0; ch < KCH; ++ch) {
        #pragma unroll
        for (int i = 0; i < 4; ++i) {
            int idx = i * 1024 + t * 4;
            int row = idx >> 5, col = idx & 31;
            float4 v = *reinterpret_cast<const float4*>(
                &A[(rowBase + row) * KD + ch * 32 + col]);
            __nv_bfloat162 h01, h23, l01, l23;
            split_bf16(v, h01, h23, l01, l23);
            *reinterpret_cast<__nv_bfloat162*>(&sA[0][row][col])     = h01;
            *reinterpret_cast<__nv_bfloat162*>(&sA[0][row][col + 2]) = h23;
            *reinterpret_cast<__nv_bfloat162*>(&sA[1][row][col])     = l01;
            *reinterpret_cast<__nv_bfloat162*>(&sA[1][row][col + 2]) = l23;
        }
        #pragma unroll
        for (int i = 0; i < BN / 32; ++i) {
            int idx = i * 1024 + t * 4;
            int row = idx >> 5, col = idx & 31;
            float4 v = *reinterpret_cast<const float4*>(
                &Bt[(long)(nBase + row) * KD + ch * 32 + col]);
            __nv_bfloat162 h01, h23, l01, l23;
            split_bf16(v, h01, h23, l01, l23);
            *reinterpret_cast<__nv_bfloat162*>(&sB[0][row][col])     = h01;
            *reinterpret_cast<__nv_bfloat162*>(&sB[0][row][col + 2]) = h23;
            *reinterpret_cast<__nv_bfloat162*>(&sB[1][row][col])     = l01;
            *reinterpret_cast<__nv_bfloat162*>(&sB[1][row][col + 2]) = l23;
        }
        __syncthreads();

        #pragma unroll
        for (int ks = 0; ks < 2; ++ks) {
            int kb = ks * 16 + 2 * tg;
            uint32_t ah[2][4], al[2][4];
            #pragma unroll
            for (int mt = 0; mt < 2; ++mt) {
                int r0 = wm * 32 + mt * 16 + g;
                ah[mt][0] = *reinterpret_cast<const uint32_t*>(&sA[0][r0][kb]);
                ah[mt][1] = *reinterpret_cast<const uint32_t*>(&sA[0][r0 + 8][kb]);
                ah[mt][2] = *reinterpret_cast<const uint32_t*>(&sA[0][r0][kb + 8]);
                ah[mt][3] = *reinterpret_cast<const uint32_t*>(&sA[0][r0 + 8][kb + 8]);
                al[mt][0] = *reinterpret_cast<const uint32_t*>(&sA[1][r0][kb]);
                al[mt][1] = *reinterpret_cast<const uint32_t*>(&sA[1][r0 + 8][kb]);
                al[mt][2] = *reinterpret_cast<const uint32_t*>(&sA[1][r0][kb + 8]);
                al[mt][3] = *reinterpret_cast<const uint32_t*>(&sA[1][r0 + 8][kb + 8]);
            }
            #pragma unroll
            for (int nt = 0; nt < NT; ++nt) {
                int n = wn * (BN / 2) + nt * 8 + g;
                uint32_t bh0 = *reinterpret_cast<const uint32_t*>(&sB[0][n][kb]);
                uint32_t bh1 = *reinterpret_cast<const uint32_t*>(&sB[0][n][kb + 8]);
                uint32_t bl0 = *reinterpret_cast<const uint32_t*>(&sB[1][n][kb]);
                uint32_t bl1 = *reinterpret_cast<const uint32_t*>(&sB[1][n][kb + 8]);
                #pragma unroll
                for (int mt = 0; mt < 2; ++mt) {
                    mma16816(acc[mt][nt], ah[mt], bh0, bh1);
                    mma16816(acc[mt][nt], ah[mt], bl0, bl1);
                    mma16816(acc[mt][nt], al[mt], bh0, bh1);
                }
            }
        }
        __syncthreads();
    }

    #pragma unroll
    for (int mt = 0; mt < 2; ++mt) {
        long row0 = rowBase + wm * 32 + mt * 16 + g;
        #pragma unroll
        for (int nt = 0; nt < NT; ++nt) {
            int col = nBase + wn * (BN / 2) + nt * 8 + 2 * tg;
            float b0 = USE_BIAS ? bias[col]     : 0.f;
            float b1 = USE_BIAS ? bias[col + 1] : 0.f;
            float v0 = acc[mt][nt][0] + b0, v1 = acc[mt][nt][1] + b1;
            float v2 = acc[mt][nt][2] + b0, v3 = acc[mt][nt][3] + b1;
            if (RELU) {
                v0 = fmaxf(v0, 0.f); v1 = fmaxf(v1, 0.f);
                v2 = fmaxf(v2, 0.f); v3 = fmaxf(v3, 0.f);
            }
            *reinterpret_cast<float2*>(&C[row0 * Nn + col])       = make_float2(v0, v1);
            *reinterpret_cast<float2*>(&C[(row0 + 8) * Nn + col]) = make_float2(v2, v3);
        }
    }
}

// ---------------- K4: fts_X = X @ [lifted|fts], then depthwise conv -> g_dw ----------------
#define PB4 8
__global__ __launch_bounds__(192) void k_xform(
        const float* __restrict__ fts,
        const float* __restrict__ dw_w, const float* __restrict__ dw_b) {
    __shared__ __align__(16) float s_Xt[16][20];   // transposed X, padded rows
    const int t = threadIdx.x;                     // 0..191 = channel c
    const int pbase = blockIdx.x * PB4;
    const int c = t;
    float wreg[DMUL][KNB];
    float breg[DMUL];
    #pragma unroll
    for (int m = 0; m < DMUL; ++m) {
        int jj = c*DMUL + m;
        breg[m] = dw_b[jj];
        #pragma unroll
        for (int k = 0; k < KNB; ++k) wreg[m][k] = dw_w[jj*KNB + k];
    }
    for (int p = 0; p < PB4; ++p) {
        int gp = pbase + p;
        for (int idx = t; idx < KKDIM; idx += 192)     // s_Xt[j][k] = X[k][j]
            s_Xt[idx & 15][idx >> 4] = g_X2[(size_t)gp*KKDIM + idx];
        __syncthreads();
        float fX[KNB];
        #pragma unroll
        for (int k = 0; k < KNB; ++k) fX[k] = 0.f;
        #pragma unroll 4
        for (int j = 0; j < KNB; ++j) {
            float catv = (c < C_MID) ? g_lift[(size_t)(gp*KNB + j)*C_MID + c]
                                     : fts[(size_t)(gp*KNB + j)*C_IN + (c - C_MID)];
            #pragma unroll
            for (int q = 0; q < 4; ++q) {
                float4 xv = *reinterpret_cast<const float4*>(&s_Xt[j][q * 4]);
                fX[q*4+0] += xv.x * catv;
                fX[q*4+1] += xv.y * catv;
                fX[q*4+2] += xv.z * catv;
                fX[q*4+3] += xv.w * catv;
            }
        }
        #pragma unroll
        for (int m = 0; m < DMUL; ++m) {
            float acc = breg[m];
            #pragma unroll
            for (int k = 0; k < KNB; ++k)
                acc += fX[k] * wreg[m][k];
            g_dw[(size_t)gp*(C_CAT*DMUL) + c*DMUL + m] = acc;
        }
        __syncthreads();
    }
}

// ---------------- K5: per-channel sum / sumsq ----------------
__global__ void k_stats(const float* __restrict__ out) {
    const int c = threadIdx.x;
    const int rows_per = NPTS / gridDim.x;
    const int r0 = blockIdx.x * rows_per;
    double s = 0.0, s2 = 0.0;
    for (int r = 0; r < rows_per; ++r) {
        float v = out[(size_t)(r0 + r)*C_OUT + c];
        s += v; s2 += (double)v * v;
    }
    atomicAdd(&g_sum[c], s);
    atomicAdd(&g_sumsq[c], s2);
}

// ---------------- K5b ----------------
__global__ void k_finstats(const float* __restrict__ bn_g, const float* __restrict__ bn_b) {
    int c = threadIdx.x;
    double inv = 1.0 / (double)NPTS;
    double mean = g_sum[c] * inv;
    double var  = g_sumsq[c] * inv - mean*mean;
    float sc = bn_g[c] * rsqrtf((float)var + EPSV);
    g_scale[c] = sc;
    g_shift[c] = bn_b[c] - (float)mean * sc;
}

// ---------------- K6: apply BN (float4) ----------------
__global__ void k_bn(float* __restrict__ out) {
    int idx = (blockIdx.x * 256 + threadIdx.x) * 4;
    int c = idx & (C_OUT - 1);
    float4 v = *reinterpret_cast<float4*>(&out[idx]);
    v.x = v.x * g_scale[c]   + g_shift[c];
    v.y = v.y * g_scale[c+1] + g_shift[c+1];
    v.z = v.z * g_scale[c+2] + g_shift[c+2];
    v.w = v.w * g_scale[c+3] + g_shift[c+3];
    *reinterpret_cast<float4*>(&out[idx]) = v;
}

// ---------------- launch ----------------
extern "C" void kernel_launch(void* const* d_in, const int* in_sizes, int n_in,
                              void* d_out, int out_size) {
    const float* rep_pt = (const float*)d_in[0];
    const float* pts    = (const float*)d_in[1];
    const float* fts    = (const float*)d_in[2];
    const float* d1_w   = (const float*)d_in[3];
    const float* d1_b   = (const float*)d_in[4];
    const float* d2_w   = (const float*)d_in[5];
    const float* d2_b   = (const float*)d_in[6];
    const float* cv_w   = (const float*)d_in[7];
    const float* cv_b   = (const float*)d_in[8];
    const float* x1_w   = (const float*)d_in[9];
    const float* x1_b   = (const float*)d_in[10];
    const float* x2_w   = (const float*)d_in[11];
    const float* x2_b   = (const float*)d_in[12];
    const float* dw_w   = (const float*)d_in[13];
    const float* dw_b   = (const float*)d_in[14];
    const float* pw_w   = (const float*)d_in[15];
    const float* bn_g   = (const float*)d_in[16];
    const float* bn_b   = (const float*)d_in[17];
    float* out = (float*)d_out;

    void *pX0, *pX1, *pX2, *pdw, *pwt1, *pwt2, *pwtd;
    cudaGetSymbolAddress(&pX0,  g_X0);
    cudaGetSymbolAddress(&pX1,  g_X1);
    cudaGetSymbolAddress(&pX2,  g_X2);
    cudaGetSymbolAddress(&pdw,  g_dw);
    cudaGetSymbolAddress(&pwt1, g_wt1);
    cudaGetSymbolAddress(&pwt2, g_wt2);
    cudaGetSymbolAddress(&pwtd, g_wtd);

    constexpr int PREP_SMEM = SPL_BYTES + 2*128*PSTR*2 + 2*64*PSTR*2;  // 53760
    cudaFuncSetAttribute(k_prep, cudaFuncAttributeMaxDynamicSharedMemorySize, PREP_SMEM);

    k_zero<<<1, 256>>>();
    k_transp<<<dim3(KKDIM/32, KKDIM/32), 256>>>(x1_w, (float*)pwt1, KKDIM, KKDIM);
    k_transp<<<dim3(KKDIM/32, KKDIM/32), 256>>>(x2_w, (float*)pwt2, KKDIM, KKDIM);
    k_transp<<<dim3(C_MID/32, C_MID/32), 256>>>(d2_w, (float*)pwtd, C_MID, C_MID);

    // fused: pts_local -> d1 -> d2 MMA -> g_lift, plus X0
    k_prep<<<NPTS/PB1, 256, PREP_SMEM>>>(rep_pt, pts, d1_w, d1_b,
                                         (const float*)pwtd, d2_b, cv_w, cv_b);

    // X1 = relu(X0 @ x1_w + x1_b):  M=16384, N=256, K=256
    k_mma<128, 256, true, true><<<dim3(2, NPTS/128), 256>>>(
        (const float*)pX0, (const float*)pwt1, x1_b, (float*)pX1, KKDIM);
    // X2 = X1 @ x2_w + x2_b
    k_mma<128, 256, false, true><<<dim3(2, NPTS/128), 256>>>(
        (const float*)pX1, (const float*)pwt2, x2_b, (float*)pX2, KKDIM);

    k_xform<<<NPTS/PB4, 192>>>(fts, dw_w, dw_b);

    // out = relu(dw @ pw_w^T):  M=16384, N=256, K=384  (pw_w already [N,K])
    k_mma<128, 384, true, false><<<dim3(2, NPTS/128), 256>>>(
        (const float*)pdw, pw_w, nullptr, out, C_OUT);

    k_stats<<<256, 256>>>(out);
    k_finstats<<<1, 256>>>(bn_g, bn_b);
    k_bn<<<(NPTS*C_OUT)/1024, 256>>>(out);
}